// round 13
// baseline (speedup 1.0000x reference)
#include <cuda_runtime.h>
#include <cstdint>

// ---------------------------------------------------------------------------
// Problem constants
// ---------------------------------------------------------------------------
#define Bv   16
#define Kv   1024
#define Mrows (Bv * Kv)            // 16384 rows of the token matrix

static const size_t ADJ_ELEMS = (size_t)Bv * 5 * Kv * Kv;   // 83,886,080

// ---------------------------------------------------------------------------
// Device scratch
// ---------------------------------------------------------------------------
__device__ float d_sup1[(size_t)Mrows * 1024];
__device__ float d_h1  [(size_t)Mrows * 1024];
__device__ float d_sup2[(size_t)Mrows * 256];
__device__ float d_h2c [(size_t)Mrows * 256];
__device__ float d_g   [(size_t)Mrows * 256];
__device__ float d_ff1 [(size_t)Mrows * 256];
__device__ float d_Wc1 [256 * 1024];   // packed layer-1 weights [k][p*512+h2*256+f]
__device__ float d_W2bd[1024 * 256];   // block-diagonal layer-2 weights
__device__ float d_bc1 [1024];
__device__ float d_bc2 [256];

// ---------------------------------------------------------------------------
// helpers
// ---------------------------------------------------------------------------
__device__ __forceinline__ uint32_t smem_to_u32(const void* p) {
    uint32_t a;
    asm("{ .reg .u64 t; cvta.to.shared.u64 t, %1; cvt.u32.u64 %0, t; }"
        : "=r"(a) : "l"(p));
    return a;
}

// tf32 rounding (RNA) so the MMA's truncating read is unbiased
__device__ __forceinline__ uint32_t f2tf(float x) {
    uint32_t r;
    asm("cvt.rna.tf32.f32 %0, %1;" : "=r"(r) : "f"(x));
    return r;
}

__device__ __forceinline__ void mma8(float* c, const uint32_t* a, const uint32_t* b) {
    asm volatile(
        "mma.sync.aligned.m16n8k8.row.col.f32.tf32.tf32.f32 "
        "{%0,%1,%2,%3},{%4,%5,%6,%7},{%8,%9},{%0,%1,%2,%3};"
        : "+f"(c[0]), "+f"(c[1]), "+f"(c[2]), "+f"(c[3])
        : "r"(a[0]), "r"(a[1]), "r"(a[2]), "r"(a[3]), "r"(b[0]), "r"(b[1]));
}

__device__ __forceinline__ void cp_async16(uint32_t dst, const void* src) {
    asm volatile("cp.async.ca.shared.global [%0], [%1], 16;"
                 :: "r"(dst), "l"(src) : "memory");
}
__device__ __forceinline__ void cp_commit() {
    asm volatile("cp.async.commit_group;" ::: "memory");
}
__device__ __forceinline__ void cp_wait2() {
    asm volatile("cp.async.wait_group 2;" ::: "memory");
}

// ---------------------------------------------------------------------------
// adj passthrough: int32 -> float32  (output doubles as fp32 adjacency source)
// ---------------------------------------------------------------------------
__global__ void conv_adj(const int* __restrict__ g, float* __restrict__ o, int n4) {
    int i = blockIdx.x * blockDim.x + threadIdx.x;
    if (i < n4) {
        int4 v = ((const int4*)g)[i];
        ((float4*)o)[i] = make_float4((float)v.x, (float)v.y, (float)v.z, (float)v.w);
    }
}

// ---------------------------------------------------------------------------
// Weight / bias packing: pair-fused layer-1 + block-diagonal layer-2
// ---------------------------------------------------------------------------
__global__ void pack_w(const float* __restrict__ Wg1, const float* __restrict__ bg1,
                       const float* __restrict__ Wg2, const float* __restrict__ bg2) {
    int i = blockIdx.x * blockDim.x + threadIdx.x;
    if (i < 256 * 1024) {
        int d = i >> 10;  int c = i & 1023;
        int p = c >> 9;   int r = c & 511;
        int h2 = r >> 8;  int f = r & 255;
        d_Wc1[i] = Wg1[(((p * 2 + h2) * 256) + d) * 256 + f];

        int j = i >> 8;  int n = i & 255;
        int pj = j >> 9; int h2j = (j >> 8) & 1; int fj = j & 255;
        int pn = n >> 7; int h2n = (n >> 6) & 1; int e = n & 63;
        float v = 0.f;
        if (pj == pn && h2j == h2n)
            v = Wg2[(((pj * 2 + h2j) * 256) + fj) * 64 + e];
        d_W2bd[i] = v;
    }
    if (i < 1024) {
        int p = i >> 9; int r = i & 511; int h2 = r >> 8; int f = r & 255;
        d_bc1[i] = bg1[(p * 2 + h2) * 256 + f];
    }
    if (i < 256) {
        int p = i >> 7; int r = i & 127; int h2 = r >> 6; int e = r & 63;
        d_bc2[i] = bg2[(p * 2 + h2) * 64 + e];
    }
}

// ---------------------------------------------------------------------------
// Adjacency GEMM, fully async, 512 threads (16 warps, 4 warps/SMSP).
// Templated on tile: BM x BN, warp grid WM x WN, warp tile
// (BM/WM) x (BN/WN), BK=32.  4-stage cp.async pipeline for both operands;
// no register staging, no cvt, no STS in the mainloop.
// A = fp32 adjacency (exact 0/1 under tf32 truncation).
// B = sup1/sup2, pre-rounded to tf32 by the producing dense GEMM epilogue.
// A smem: m-major BMx32 with 16B-quad XOR swizzle (conflict-free frags).
// B smem: k-major [32][BN+8] (conflict-free: (BN+8) mod 32 = 8).
// blockIdx.z = p*16 + b selects adjacency slice (p?4:1) and column pair.
// ---------------------------------------------------------------------------
template<int BM, int BN, int WM, int WN, bool RELU>
__global__ __launch_bounds__(WM * WN * 32, 1)
void adj_gemm_async(const float* __restrict__ Aall,
                    const float* __restrict__ W, int ldw,
                    const float* __restrict__ bias,
                    float* __restrict__ C, int ldc, int Nloc)
{
    constexpr int T    = WM * WN * 32;    // threads
    constexpr int MT   = BM / WM / 16;    // 16-row m-tiles per warp
    constexpr int NTW  = BN / WN / 8;     // 8-col n-tiles per warp
    constexpr int BSTR = BN + 8;
    constexpr int ASZ  = BM * 32;         // floats
    constexpr int BSZ  = 32 * BSTR;       // floats
    constexpr int STG  = ASZ + BSZ;
    constexpr int CA   = BM * 8 / T;      // A 16B-chunks per thread
    constexpr int CB   = 8 * BN / T;      // B 16B-chunks per thread

    extern __shared__ float smf[];
    const uint32_t sbase = smem_to_u32(smf);

    const int tid  = threadIdx.x;
    const int lane = tid & 31;
    const int wid  = tid >> 5;
    const int warp_m = wid % WM;
    const int warp_n = wid / WM;
    const int bm = blockIdx.y * BM;
    const int bn = blockIdx.x * BN;

    const int z = blockIdx.z;
    const int p = z >> 4;
    const int b = z & 15;
    const int slice = p ? 4 : 1;
    const float* Ap = Aall + ((size_t)(b * 5 + slice)) * Kv * Kv;
    const float* Wp = W + (size_t)b * Kv * ldw + p * Nloc;
    float*       Cp = C + (size_t)b * Kv * ldc + p * Nloc;
    const float* bp = bias + p * Nloc;

    const int brow = tid >> 4;            // 0..31 : B k-row (T=512)
    const int bseg = tid & 15;            // B 16B-seg group

    auto issue = [&](int s, int k0) {
        uint32_t ab = sbase + s * (STG * 4);
        #pragma unroll
        for (int i = 0; i < CA; i++) {
            int chunk = i * T + tid;
            int r  = chunk >> 3;
            int kq = chunk & 7;
            cp_async16(ab + (r * 32 + ((kq ^ (r & 7)) << 2)) * 4,
                       Ap + (size_t)(bm + r) * Kv + k0 + kq * 4);
        }
        uint32_t bb = ab + ASZ * 4;
        #pragma unroll
        for (int u = 0; u < CB; u++) {
            int col = (bseg + u * 16) * 4;
            cp_async16(bb + (brow * BSTR + col) * 4,
                       Wp + (size_t)(k0 + brow) * ldw + bn + col);
        }
        cp_commit();
    };

    float acc[MT][NTW][4] = {};
    const int q  = lane & 3;
    const int rl = lane >> 2;

    constexpr int nchunks = Kv / 32;      // 32
    issue(0, 0);
    issue(1, 32);

    for (int c = 0; c < nchunks; c++) {
        if (c + 2 < nchunks) issue((c + 2) & 3, (c + 2) * 32);
        cp_wait2();
        __syncthreads();

        const float* Ab = smf + (c & 3) * STG;
        const float* Bb = Ab + ASZ;
        #pragma unroll
        for (int kk = 0; kk < 4; kk++) {
            uint32_t af[MT][4];
            uint32_t bf[NTW][2];
            const int kq0 = kk * 2;
            #pragma unroll
            for (int mt = 0; mt < MT; mt++) {
                int r0 = warp_m * (MT * 16) + mt * 16 + rl;
                int r1 = r0 + 8;
                af[mt][0] = __float_as_uint(Ab[r0 * 32 + (((kq0    ) ^ (r0 & 7)) << 2) + q]);
                af[mt][1] = __float_as_uint(Ab[r1 * 32 + (((kq0    ) ^ (r1 & 7)) << 2) + q]);
                af[mt][2] = __float_as_uint(Ab[r0 * 32 + (((kq0 + 1) ^ (r0 & 7)) << 2) + q]);
                af[mt][3] = __float_as_uint(Ab[r1 * 32 + (((kq0 + 1) ^ (r1 & 7)) << 2) + q]);
            }
            const int kA = kk * 8 + q;
            #pragma unroll
            for (int nt = 0; nt < NTW; nt++) {
                int cc = warp_n * (NTW * 8) + nt * 8 + rl;
                bf[nt][0] = __float_as_uint(Bb[(kA    ) * BSTR + cc]);
                bf[nt][1] = __float_as_uint(Bb[(kA + 4) * BSTR + cc]);
            }
            #pragma unroll
            for (int mt = 0; mt < MT; mt++)
                #pragma unroll
                for (int nt = 0; nt < NTW; nt++)
                    mma8(acc[mt][nt], af[mt], bf[nt]);
        }
    }

    // ---- epilogue ----
    #pragma unroll
    for (int mt = 0; mt < MT; mt++) {
        const int row = bm + warp_m * (MT * 16) + mt * 16 + rl;
        #pragma unroll
        for (int nt = 0; nt < NTW; nt++) {
            const int col = bn + warp_n * (NTW * 8) + nt * 8 + 2 * q;
            float b0 = bp[col], b1 = bp[col + 1];
            float v0 = acc[mt][nt][0] + b0, v1 = acc[mt][nt][1] + b1;
            float v2 = acc[mt][nt][2] + b0, v3 = acc[mt][nt][3] + b1;
            if (RELU) {
                v0 = fmaxf(v0, 0.f); v1 = fmaxf(v1, 0.f);
                v2 = fmaxf(v2, 0.f); v3 = fmaxf(v3, 0.f);
            }
            *(float2*)&Cp[(size_t)row * ldc + col] = make_float2(v0, v1);
            *(float2*)&Cp[(size_t)(row + 8) * ldc + col] = make_float2(v2, v3);
        }
    }
}

// ---------------------------------------------------------------------------
// Dense tf32 GEMM (register-staged A/B with RNA rounding), 64x64 warp tiles,
// 256 threads.  ROUND: round outputs to tf32 (RNA) so consumers can cp.async
// them directly.
// ---------------------------------------------------------------------------
template<int NT, bool RELU, bool RES, bool ROUND>
__global__ __launch_bounds__(256, 1)
void dense_gemm(const float* __restrict__ Av, int lda,
                const float* __restrict__ W, int ldw,
                const float* __restrict__ bias,
                const float* __restrict__ res, int ldres,
                float* __restrict__ C, int ldc,
                int Kd)
{
    constexpr int BN   = NT * 32;
    constexpr int BSTR = BN + 8;
    constexpr int ASZ  = 128 * 32;
    constexpr int BSZ  = 32 * BSTR;
    constexpr int STG  = ASZ + BSZ;

    extern __shared__ float smf[];

    const int tid  = threadIdx.x;
    const int lane = tid & 31;
    const int wid  = tid >> 5;
    const int warp_m = wid & 1;
    const int warp_n = wid >> 1;
    const int bm = blockIdx.y * 128;
    const int bn = blockIdx.x * BN;

    float* Abuf0 = smf;
    float* Bbuf0 = smf + ASZ;

    const int brow = tid >> 3;
    const int bc0  = (tid & 7) * 4;

    float4 Areg[4];
    float4 Breg[NT];

    auto ldgA = [&](int k0) {
        #pragma unroll
        for (int i = 0; i < 4; i++) {
            int chunk = i * 256 + tid;
            int r  = chunk >> 3;
            int kq = chunk & 7;
            Areg[i] = *(const float4*)(Av + (size_t)(bm + r) * lda + k0 + kq * 4);
        }
    };
    auto stsA = [&](int s) {
        float* ab = Abuf0 + s * STG;
        #pragma unroll
        for (int i = 0; i < 4; i++) {
            int chunk = i * 256 + tid;
            int r  = chunk >> 3;
            int kq = chunk & 7;
            uint4 v;
            v.x = f2tf(Areg[i].x); v.y = f2tf(Areg[i].y);
            v.z = f2tf(Areg[i].z); v.w = f2tf(Areg[i].w);
            *(uint4*)(ab + r * 32 + ((kq ^ (r & 7)) << 2)) = v;
        }
    };
    auto ldgB = [&](int k0) {
        const float* wr = W + (size_t)(k0 + brow) * ldw + bn + bc0;
        #pragma unroll
        for (int u = 0; u < NT; u++)
            Breg[u] = *(const float4*)(wr + u * 32);
    };
    auto stsB = [&](int s) {
        float* bb = Bbuf0 + s * STG;
        #pragma unroll
        for (int u = 0; u < NT; u++) {
            uint4 v;
            v.x = f2tf(Breg[u].x); v.y = f2tf(Breg[u].y);
            v.z = f2tf(Breg[u].z); v.w = f2tf(Breg[u].w);
            *(uint4*)(bb + brow * BSTR + bc0 + u * 32) = v;
        }
    };

    float acc[4][NT][4] = {};

    ldgA(0);
    ldgB(0);
    stsA(0);
    stsB(0);
    __syncthreads();

    const int nchunks = Kd >> 5;
    const int q  = lane & 3;
    const int rl = lane >> 2;

    for (int c = 0; c < nchunks; c++) {
        const int s = c & 1;
        const bool pf = (c + 1 < nchunks);
        if (pf) {
            ldgA((c + 1) * 32);
            ldgB((c + 1) * 32);
        }

        const float* Ab = Abuf0 + s * STG;
        const float* Bb = Bbuf0 + s * STG;
        #pragma unroll
        for (int kk = 0; kk < 4; kk++) {
            uint32_t af[4][4];
            uint32_t bf[NT][2];
            const int kq0 = kk * 2;
            #pragma unroll
            for (int mt = 0; mt < 4; mt++) {
                int r0 = warp_m * 64 + mt * 16 + rl;
                int r1 = r0 + 8;
                af[mt][0] = __float_as_uint(Ab[r0 * 32 + (((kq0    ) ^ (r0 & 7)) << 2) + q]);
                af[mt][1] = __float_as_uint(Ab[r1 * 32 + (((kq0    ) ^ (r1 & 7)) << 2) + q]);
                af[mt][2] = __float_as_uint(Ab[r0 * 32 + (((kq0 + 1) ^ (r0 & 7)) << 2) + q]);
                af[mt][3] = __float_as_uint(Ab[r1 * 32 + (((kq0 + 1) ^ (r1 & 7)) << 2) + q]);
            }
            const int kA = kk * 8 + q;
            #pragma unroll
            for (int nt = 0; nt < NT; nt++) {
                int cc = warp_n * (NT * 8) + nt * 8 + rl;
                bf[nt][0] = __float_as_uint(Bb[(kA    ) * BSTR + cc]);
                bf[nt][1] = __float_as_uint(Bb[(kA + 4) * BSTR + cc]);
            }
            #pragma unroll
            for (int mt = 0; mt < 4; mt++)
                #pragma unroll
                for (int nt = 0; nt < NT; nt++)
                    mma8(acc[mt][nt], af[mt], bf[nt]);
        }

        if (pf) {
            stsA(s ^ 1);
            stsB(s ^ 1);
            __syncthreads();
        }
    }

    #pragma unroll
    for (int mt = 0; mt < 4; mt++) {
        const int row = bm + warp_m * 64 + mt * 16 + rl;
        #pragma unroll
        for (int nt = 0; nt < NT; nt++) {
            const int col = bn + warp_n * (NT * 8) + nt * 8 + 2 * q;
            float b0 = 0.f, b1 = 0.f;
            if (bias) { b0 = bias[col]; b1 = bias[col + 1]; }
            float v0 = acc[mt][nt][0] + b0, v1 = acc[mt][nt][1] + b1;
            float v2 = acc[mt][nt][2] + b0, v3 = acc[mt][nt][3] + b1;
            if (RELU) {
                v0 = fmaxf(v0, 0.f); v1 = fmaxf(v1, 0.f);
                v2 = fmaxf(v2, 0.f); v3 = fmaxf(v3, 0.f);
            }
            if (RES) {
                const float* r0p = res + (size_t)row * ldres + col;
                const float* r1p = res + (size_t)(row + 8) * ldres + col;
                v0 += r0p[0]; v1 += r0p[1]; v2 += r1p[0]; v3 += r1p[1];
            }
            if (ROUND) {
                v0 = __uint_as_float(f2tf(v0)); v1 = __uint_as_float(f2tf(v1));
                v2 = __uint_as_float(f2tf(v2)); v3 = __uint_as_float(f2tf(v3));
            }
            *(float2*)&C[(size_t)row * ldc + col] = make_float2(v0, v1);
            *(float2*)&C[(size_t)(row + 8) * ldc + col] = make_float2(v2, v3);
        }
    }
}

// ---------------------------------------------------------------------------
// LayerNorm (MWPToolkit: a*(x-mu)/(std_ddof1 + eps) + b) + residual
// ---------------------------------------------------------------------------
__global__ __launch_bounds__(256)
void ln_kernel(const float* __restrict__ x, const float* __restrict__ nodes,
               const float* __restrict__ ln_a, const float* __restrict__ ln_b,
               float* __restrict__ g)
{
    int warp = (blockIdx.x * blockDim.x + threadIdx.x) >> 5;
    int lane = threadIdx.x & 31;
    if (warp >= Mrows) return;
    const float* xr = x + (size_t)warp * 256;
    float v[8];
    float s = 0.f, ss = 0.f;
    #pragma unroll
    for (int j = 0; j < 8; j++) {
        v[j] = xr[lane + j * 32];
        s += v[j];
        ss += v[j] * v[j];
    }
    #pragma unroll
    for (int o = 16; o; o >>= 1) {
        s  += __shfl_xor_sync(0xffffffffu, s, o);
        ss += __shfl_xor_sync(0xffffffffu, ss, o);
    }
    float mu  = s * (1.f / 256.f);
    float var = (ss - 256.f * mu * mu) * (1.f / 255.f);
    float inv = 1.f / (sqrtf(fmaxf(var, 0.f)) + 1e-6f);
    const float* nd = nodes + (size_t)warp * 256;
    float* go = g + (size_t)warp * 256;
    #pragma unroll
    for (int j = 0; j < 8; j++) {
        int c = lane + j * 32;
        go[c] = ln_a[c] * (v[j] - mu) * inv + ln_b[c] + nd[c];
    }
}

// ---------------------------------------------------------------------------
// Launcher
// ---------------------------------------------------------------------------
extern "C" void kernel_launch(void* const* d_in, const int* in_sizes, int n_in,
                              void* d_out, int out_size)
{
    const float* nodes = (const float*)d_in[0];
    const int*   graph = (const int*)d_in[1];
    const float* Wg1   = (const float*)d_in[2];
    const float* bg1   = (const float*)d_in[3];
    const float* Wg2   = (const float*)d_in[4];
    const float* bg2   = (const float*)d_in[5];
    const float* Wf1   = (const float*)d_in[6];
    const float* bf1   = (const float*)d_in[7];
    const float* Wf2   = (const float*)d_in[8];
    const float* bf2   = (const float*)d_in[9];
    const float* ln_a  = (const float*)d_in[10];
    const float* ln_b  = (const float*)d_in[11];
    float* out = (float*)d_out;

    float *sup1, *h1, *sup2, *h2c, *g, *ff1, *Wc1, *W2bd, *bc1, *bc2;
    cudaGetSymbolAddress((void**)&sup1, d_sup1);
    cudaGetSymbolAddress((void**)&h1,   d_h1);
    cudaGetSymbolAddress((void**)&sup2, d_sup2);
    cudaGetSymbolAddress((void**)&h2c,  d_h2c);
    cudaGetSymbolAddress((void**)&g,    d_g);
    cudaGetSymbolAddress((void**)&ff1,  d_ff1);
    cudaGetSymbolAddress((void**)&Wc1,  d_Wc1);
    cudaGetSymbolAddress((void**)&W2bd, d_W2bd);
    cudaGetSymbolAddress((void**)&bc1,  d_bc1);
    cudaGetSymbolAddress((void**)&bc2,  d_bc2);

    // adj stage bytes: BM=128/BN=256 and BM=256/BN=128 both = 50,176 B
    const int ADJSTG = (128 * 32 + 32 * (256 + 8)) * 4;   // 50,176 B
    const int ADJSM  = 4 * ADJSTG;                        // 200,704 B
    const int DEN8   = 2 * ADJSTG;                        // 100,352 B
    cudaFuncSetAttribute((const void*)adj_gemm_async<128, 256, 4, 4, true>,
                         cudaFuncAttributeMaxDynamicSharedMemorySize, ADJSM);
    cudaFuncSetAttribute((const void*)adj_gemm_async<256, 128, 4, 4, false>,
                         cudaFuncAttributeMaxDynamicSharedMemorySize, ADJSM);
    cudaFuncSetAttribute((const void*)dense_gemm<8, false, false, true>,
                         cudaFuncAttributeMaxDynamicSharedMemorySize, DEN8);
    cudaFuncSetAttribute((const void*)dense_gemm<8, true, false, false>,
                         cudaFuncAttributeMaxDynamicSharedMemorySize, DEN8);
    cudaFuncSetAttribute((const void*)dense_gemm<8, false, true, false>,
                         cudaFuncAttributeMaxDynamicSharedMemorySize, DEN8);

    // 0) adj passthrough (int -> float); output also serves as fp32 adjacency
    conv_adj<<<81920, 256>>>(graph, out, (int)(ADJ_ELEMS / 4));

    // 1) weight packing
    pack_w<<<1024, 256>>>(Wg1, bg1, Wg2, bg2);

    // 2) sup1 = nodes @ Wc1 (tf32-rounded output)   (16384x256)@(256x1024)
    dense_gemm<8, false, false, true><<<dim3(4, 128, 1), 256, DEN8>>>(
        nodes, 256, Wc1, 1024, nullptr, nullptr, 0, sup1, 1024, 256);

    // 3) h1 = relu(adj @ sup1 + bc1)   32 batches of (1024x1024)@(1024x512)
    //    512 threads, warp tile 32x64, grid 2x8x32 = 512 CTAs
    adj_gemm_async<128, 256, 4, 4, true><<<dim3(2, 8, 32), 512, ADJSM>>>(
        out, sup1, 1024, bc1, h1, 1024, 512);

    // 4) sup2 = h1 @ W2bd (tf32-rounded output)     (16384x1024)@(1024x256)
    dense_gemm<8, false, false, true><<<dim3(1, 128, 1), 256, DEN8>>>(
        h1, 1024, W2bd, 256, nullptr, nullptr, 0, sup2, 256, 1024);

    // 5) h2 = adj @ sup2 + bc2         32 batches of (1024x1024)@(1024x128)
    //    512 threads, warp tile 64x32, grid 1x4x32 = 128 CTAs (single wave)
    adj_gemm_async<256, 128, 4, 4, false><<<dim3(1, 4, 32), 512, ADJSM>>>(
        out, sup2, 256, bc2, h2c, 256, 128);

    // 6) g = LN(h2cat) + nodes
    ln_kernel<<<2048, 256>>>(h2c, nodes, ln_a, ln_b, g);

    // 7) ff1 = relu(g @ Wf1 + bf1)
    dense_gemm<8, true, false, false><<<dim3(1, 128, 1), 256, DEN8>>>(
        g, 256, Wf1, 256, bf1, nullptr, 0, ff1, 256, 256);

    // 8) out = ff1 @ Wf2 + bf2 + g
    dense_gemm<8, false, true, false><<<dim3(1, 128, 1), 256, DEN8>>>(
        ff1, 256, Wf2, 256, bf2, g, 256, out + ADJ_ELEMS, 256, 256);
}

// round 16
// speedup vs baseline: 1.4229x; 1.4229x over previous
#include <cuda_runtime.h>
#include <cuda_fp16.h>
#include <cstdint>

// ---------------------------------------------------------------------------
// Problem constants
// ---------------------------------------------------------------------------
#define Bv   16
#define Kv   1024
#define Mrows (Bv * Kv)            // 16384 rows of the token matrix

static const size_t ADJ_ELEMS = (size_t)Bv * 5 * Kv * Kv;   // 83,886,080

// ---------------------------------------------------------------------------
// Device scratch
// ---------------------------------------------------------------------------
__device__ __half d_adjh [(size_t)2 * 16 * 1024 * 1024];  // fp16 adjacency, slices {1,4}
__device__ __half d_sup1t[(size_t)1024 * Mrows];          // sup1^T [n][m] fp16
__device__ __half d_sup2t[(size_t)256 * Mrows];           // sup2^T [n][m] fp16
__device__ float  d_h1  [(size_t)Mrows * 1024];
__device__ float  d_h2c [(size_t)Mrows * 256];
__device__ float  d_g   [(size_t)Mrows * 256];
__device__ float  d_ff1 [(size_t)Mrows * 256];
__device__ float  d_Wc1 [256 * 1024];   // packed layer-1 weights
__device__ float  d_W2bd[1024 * 256];   // block-diagonal layer-2 weights
__device__ float  d_bc1 [1024];
__device__ float  d_bc2 [256];

// ---------------------------------------------------------------------------
// helpers
// ---------------------------------------------------------------------------
__device__ __forceinline__ uint32_t smem_to_u32(const void* p) {
    uint32_t a;
    asm("{ .reg .u64 t; cvta.to.shared.u64 t, %1; cvt.u32.u64 %0, t; }"
        : "=r"(a) : "l"(p));
    return a;
}

__device__ __forceinline__ uint32_t f2tf(float x) {
    uint32_t r;
    asm("cvt.rna.tf32.f32 %0, %1;" : "=r"(r) : "f"(x));
    return r;
}

__device__ __forceinline__ void mma8(float* c, const uint32_t* a, const uint32_t* b) {
    asm volatile(
        "mma.sync.aligned.m16n8k8.row.col.f32.tf32.tf32.f32 "
        "{%0,%1,%2,%3},{%4,%5,%6,%7},{%8,%9},{%0,%1,%2,%3};"
        : "+f"(c[0]), "+f"(c[1]), "+f"(c[2]), "+f"(c[3])
        : "r"(a[0]), "r"(a[1]), "r"(a[2]), "r"(a[3]), "r"(b[0]), "r"(b[1]));
}

__device__ __forceinline__ void mma16(float* c, const uint32_t* a, const uint32_t* b) {
    asm volatile(
        "mma.sync.aligned.m16n8k16.row.col.f32.f16.f16.f32 "
        "{%0,%1,%2,%3},{%4,%5,%6,%7},{%8,%9},{%0,%1,%2,%3};"
        : "+f"(c[0]), "+f"(c[1]), "+f"(c[2]), "+f"(c[3])
        : "r"(a[0]), "r"(a[1]), "r"(a[2]), "r"(a[3]), "r"(b[0]), "r"(b[1]));
}

__device__ __forceinline__ void cp_async16(uint32_t dst, const void* src) {
    asm volatile("cp.async.ca.shared.global [%0], [%1], 16;"
                 :: "r"(dst), "l"(src) : "memory");
}
__device__ __forceinline__ void cp_commit() {
    asm volatile("cp.async.commit_group;" ::: "memory");
}
__device__ __forceinline__ void cp_wait2() {
    asm volatile("cp.async.wait_group 2;" ::: "memory");
}

// ---------------------------------------------------------------------------
// adj passthrough: int32 -> float32 output, PLUS fp16 copy of slices 1 and 4
// ---------------------------------------------------------------------------
__global__ void conv_adj(const int* __restrict__ g, float* __restrict__ o,
                         __half* __restrict__ ah, int n4) {
    int i = blockIdx.x * blockDim.x + threadIdx.x;
    if (i < n4) {
        int4 v = ((const int4*)g)[i];
        ((float4*)o)[i] = make_float4((float)v.x, (float)v.y, (float)v.z, (float)v.w);
        int e  = i * 4;            // element index (fits in int: 83.9M)
        int bs = e >> 20;          // (b*5 + s)
        int s  = bs % 5;
        if (s == 1 || s == 4) {
            int b = bs / 5;
            int pair = (s == 4) ? 1 : 0;
            size_t dst = ((size_t)(pair * 16 + b) << 20) + (e & 0xFFFFF);
            __half2 h01 = __floats2half2_rn((float)v.x, (float)v.y);
            __half2 h23 = __floats2half2_rn((float)v.z, (float)v.w);
            *(__half2*)(ah + dst)     = h01;
            *(__half2*)(ah + dst + 2) = h23;
        }
    }
}

// ---------------------------------------------------------------------------
// Weight / bias packing: pair-fused layer-1 + block-diagonal layer-2
// ---------------------------------------------------------------------------
__global__ void pack_w(const float* __restrict__ Wg1, const float* __restrict__ bg1,
                       const float* __restrict__ Wg2, const float* __restrict__ bg2) {
    int i = blockIdx.x * blockDim.x + threadIdx.x;
    if (i < 256 * 1024) {
        int d = i >> 10;  int c = i & 1023;
        int p = c >> 9;   int r = c & 511;
        int h2 = r >> 8;  int f = r & 255;
        d_Wc1[i] = Wg1[(((p * 2 + h2) * 256) + d) * 256 + f];

        int j = i >> 8;  int n = i & 255;
        int pj = j >> 9; int h2j = (j >> 8) & 1; int fj = j & 255;
        int pn = n >> 7; int h2n = (n >> 6) & 1; int e = n & 63;
        float v = 0.f;
        if (pj == pn && h2j == h2n)
            v = Wg2[(((pj * 2 + h2j) * 256) + fj) * 64 + e];
        d_W2bd[i] = v;
    }
    if (i < 1024) {
        int p = i >> 9; int r = i & 511; int h2 = r >> 8; int f = r & 255;
        d_bc1[i] = bg1[(p * 2 + h2) * 256 + f];
    }
    if (i < 256) {
        int p = i >> 7; int r = i & 127; int h2 = r >> 6; int e = r & 63;
        d_bc2[i] = bg2[(p * 2 + h2) * 64 + e];
    }
}

// ---------------------------------------------------------------------------
// fp16 adjacency GEMM.  BM x BN block, 256 threads (8 warps WM x WN),
// warp tile (BM/WM) x (BN/WN), BK=64 halfs, mma.m16n8k16.f16.f32acc.
// A smem: m-major BM rows x 128B (64 halfs), XOR-quad swizzle.
// B smem: n-major BN rows x 128B (64 k-halfs), same swizzle; fed straight
//   from sup1t/sup2t (fp16, n-major in gmem) via cp.async — no staging ops.
// A = fp16 adjacency (0/1 exact).  4-stage cp.async pipeline.
// blockIdx.z = p*16 + b.
// ---------------------------------------------------------------------------
template<int BM, int BN, int WM, int WN, bool RELU>
__global__ __launch_bounds__(256, 1)
void adj_gemm_h16(const __half* __restrict__ Aall,
                  const __half* __restrict__ Bt,      // [Ncols][16384] fp16
                  const float* __restrict__ bias,
                  float* __restrict__ C, int ldc, int Nloc)
{
    constexpr int MT   = BM / WM / 16;    // 16-row m-tiles per warp
    constexpr int NTW  = BN / WN / 8;     // 8-col n-tiles per warp
    constexpr int ABYT = BM * 128;        // A stage bytes
    constexpr int BBYT = BN * 128;        // B stage bytes
    constexpr int STGB = ABYT + BBYT;
    constexpr int CA   = BM * 8 / 256;    // A 16B segs per thread
    constexpr int CB   = BN * 8 / 256;    // B 16B segs per thread

    extern __shared__ char smc[];
    const uint32_t sbase = smem_to_u32(smc);

    const int tid  = threadIdx.x;
    const int lane = tid & 31;
    const int wid  = tid >> 5;
    const int warp_m = wid % WM;
    const int warp_n = wid / WM;
    const int bm = blockIdx.y * BM;
    const int bn = blockIdx.x * BN;

    const int z = blockIdx.z;
    const int p = z >> 4;
    const int b = z & 15;
    const __half* Ap = Aall + (((size_t)(p * 16 + b)) << 20);
    const __half* Bp = Bt + (size_t)(p * Nloc + bn) * Mrows + b * Kv;
    float*        Cp = C + (size_t)b * Kv * ldc + p * Nloc;
    const float*  bp = bias + p * Nloc;

    auto issue = [&](int s, int k0) {
        uint32_t ab = sbase + s * STGB;
        #pragma unroll
        for (int i = 0; i < CA; i++) {
            int c = i * 256 + tid;
            int r = c >> 3, seg = c & 7;
            cp_async16(ab + r * 128 + ((seg ^ (r & 7)) << 4),
                       Ap + (size_t)(bm + r) * Kv + k0 + seg * 8);
        }
        uint32_t bb = ab + ABYT;
        #pragma unroll
        for (int i = 0; i < CB; i++) {
            int c = i * 256 + tid;
            int r = c >> 3, seg = c & 7;
            cp_async16(bb + r * 128 + ((seg ^ (r & 7)) << 4),
                       Bp + (size_t)r * Mrows + k0 + seg * 8);
        }
        cp_commit();
    };

    float acc[MT][NTW][4] = {};
    const int q  = lane & 3;
    const int rl = lane >> 2;

    constexpr int nchunks = Kv / 64;      // 16
    issue(0, 0);
    issue(1, 64);

    for (int c = 0; c < nchunks; c++) {
        if (c + 2 < nchunks) issue((c + 2) & 3, (c + 2) * 64);
        cp_wait2();
        __syncthreads();

        const char* Ab = smc + (c & 3) * STGB;
        const char* Bb = Ab + ABYT;
        #pragma unroll
        for (int kk = 0; kk < 4; kk++) {
            uint32_t af[MT][4];
            uint32_t bf[NTW][2];
            #pragma unroll
            for (int mt = 0; mt < MT; mt++) {
                int r0 = warp_m * (MT * 16) + mt * 16 + rl;
                int r1 = r0 + 8;
                int q0 = (2 * kk) ^ (r0 & 7);       // r0&7 == r1&7
                int q1 = (2 * kk + 1) ^ (r0 & 7);
                af[mt][0] = *(const uint32_t*)(Ab + r0 * 128 + (q0 << 4) + 4 * q);
                af[mt][1] = *(const uint32_t*)(Ab + r1 * 128 + (q0 << 4) + 4 * q);
                af[mt][2] = *(const uint32_t*)(Ab + r0 * 128 + (q1 << 4) + 4 * q);
                af[mt][3] = *(const uint32_t*)(Ab + r1 * 128 + (q1 << 4) + 4 * q);
            }
            #pragma unroll
            for (int nt = 0; nt < NTW; nt++) {
                int c0 = warp_n * (NTW * 8) + nt * 8 + rl;
                int q0 = (2 * kk) ^ (c0 & 7);
                int q1 = (2 * kk + 1) ^ (c0 & 7);
                bf[nt][0] = *(const uint32_t*)(Bb + c0 * 128 + (q0 << 4) + 4 * q);
                bf[nt][1] = *(const uint32_t*)(Bb + c0 * 128 + (q1 << 4) + 4 * q);
            }
            #pragma unroll
            for (int mt = 0; mt < MT; mt++)
                #pragma unroll
                for (int nt = 0; nt < NTW; nt++)
                    mma16(acc[mt][nt], af[mt], bf[nt]);
        }
    }

    // ---- epilogue (fp32 out) ----
    #pragma unroll
    for (int mt = 0; mt < MT; mt++) {
        const int row = bm + warp_m * (MT * 16) + mt * 16 + rl;
        #pragma unroll
        for (int nt = 0; nt < NTW; nt++) {
            const int col = bn + warp_n * (NTW * 8) + nt * 8 + 2 * q;
            float b0 = bp[col], b1 = bp[col + 1];
            float v0 = acc[mt][nt][0] + b0, v1 = acc[mt][nt][1] + b1;
            float v2 = acc[mt][nt][2] + b0, v3 = acc[mt][nt][3] + b1;
            if (RELU) {
                v0 = fmaxf(v0, 0.f); v1 = fmaxf(v1, 0.f);
                v2 = fmaxf(v2, 0.f); v3 = fmaxf(v3, 0.f);
            }
            *(float2*)&Cp[(size_t)row * ldc + col] = make_float2(v0, v1);
            *(float2*)&Cp[(size_t)(row + 8) * ldc + col] = make_float2(v2, v3);
        }
    }
}

// ---------------------------------------------------------------------------
// Dense tf32 GEMM (register-staged A/B with RNA rounding), 64x64 warp tiles,
// 256 threads.  TRANSH: write C transposed as fp16 into Ct[n][m] (consumed by
// the fp16 adjacency GEMM); no fp32 C write in that mode.
// ---------------------------------------------------------------------------
template<int NT, bool RELU, bool RES, bool TRANSH>
__global__ __launch_bounds__(256, 1)
void dense_gemm(const float* __restrict__ Av, int lda,
                const float* __restrict__ W, int ldw,
                const float* __restrict__ bias,
                const float* __restrict__ res, int ldres,
                float* __restrict__ C, int ldc,
                __half* __restrict__ Ct,
                int Kd)
{
    constexpr int BN   = NT * 32;
    constexpr int BSTR = BN + 8;
    constexpr int ASZ  = 128 * 32;
    constexpr int BSZ  = 32 * BSTR;
    constexpr int STG  = ASZ + BSZ;

    extern __shared__ float smf[];

    const int tid  = threadIdx.x;
    const int lane = tid & 31;
    const int wid  = tid >> 5;
    const int warp_m = wid & 1;
    const int warp_n = wid >> 1;
    const int bm = blockIdx.y * 128;
    const int bn = blockIdx.x * BN;

    float* Abuf0 = smf;
    float* Bbuf0 = smf + ASZ;

    const int brow = tid >> 3;
    const int bc0  = (tid & 7) * 4;

    float4 Areg[4];
    float4 Breg[NT];

    auto ldgA = [&](int k0) {
        #pragma unroll
        for (int i = 0; i < 4; i++) {
            int chunk = i * 256 + tid;
            int r  = chunk >> 3;
            int kq = chunk & 7;
            Areg[i] = *(const float4*)(Av + (size_t)(bm + r) * lda + k0 + kq * 4);
        }
    };
    auto stsA = [&](int s) {
        float* ab = Abuf0 + s * STG;
        #pragma unroll
        for (int i = 0; i < 4; i++) {
            int chunk = i * 256 + tid;
            int r  = chunk >> 3;
            int kq = chunk & 7;
            uint4 v;
            v.x = f2tf(Areg[i].x); v.y = f2tf(Areg[i].y);
            v.z = f2tf(Areg[i].z); v.w = f2tf(Areg[i].w);
            *(uint4*)(ab + r * 32 + ((kq ^ (r & 7)) << 2)) = v;
        }
    };
    auto ldgB = [&](int k0) {
        const float* wr = W + (size_t)(k0 + brow) * ldw + bn + bc0;
        #pragma unroll
        for (int u = 0; u < NT; u++)
            Breg[u] = *(const float4*)(wr + u * 32);
    };
    auto stsB = [&](int s) {
        float* bb = Bbuf0 + s * STG;
        #pragma unroll
        for (int u = 0; u < NT; u++) {
            uint4 v;
            v.x = f2tf(Breg[u].x); v.y = f2tf(Breg[u].y);
            v.z = f2tf(Breg[u].z); v.w = f2tf(Breg[u].w);
            *(uint4*)(bb + brow * BSTR + bc0 + u * 32) = v;
        }
    };

    float acc[4][NT][4] = {};

    ldgA(0);
    ldgB(0);
    stsA(0);
    stsB(0);
    __syncthreads();

    const int nchunks = Kd >> 5;
    const int q  = lane & 3;
    const int rl = lane >> 2;

    for (int c = 0; c < nchunks; c++) {
        const int s = c & 1;
        const bool pf = (c + 1 < nchunks);
        if (pf) {
            ldgA((c + 1) * 32);
            ldgB((c + 1) * 32);
        }

        const float* Ab = Abuf0 + s * STG;
        const float* Bb = Bbuf0 + s * STG;
        #pragma unroll
        for (int kk = 0; kk < 4; kk++) {
            uint32_t af[4][4];
            uint32_t bf[NT][2];
            const int kq0 = kk * 2;
            #pragma unroll
            for (int mt = 0; mt < 4; mt++) {
                int r0 = warp_m * 64 + mt * 16 + rl;
                int r1 = r0 + 8;
                af[mt][0] = __float_as_uint(Ab[r0 * 32 + (((kq0    ) ^ (r0 & 7)) << 2) + q]);
                af[mt][1] = __float_as_uint(Ab[r1 * 32 + (((kq0    ) ^ (r1 & 7)) << 2) + q]);
                af[mt][2] = __float_as_uint(Ab[r0 * 32 + (((kq0 + 1) ^ (r0 & 7)) << 2) + q]);
                af[mt][3] = __float_as_uint(Ab[r1 * 32 + (((kq0 + 1) ^ (r1 & 7)) << 2) + q]);
            }
            const int kA = kk * 8 + q;
            #pragma unroll
            for (int nt = 0; nt < NT; nt++) {
                int cc = warp_n * (NT * 8) + nt * 8 + rl;
                bf[nt][0] = __float_as_uint(Bb[(kA    ) * BSTR + cc]);
                bf[nt][1] = __float_as_uint(Bb[(kA + 4) * BSTR + cc]);
            }
            #pragma unroll
            for (int mt = 0; mt < 4; mt++)
                #pragma unroll
                for (int nt = 0; nt < NT; nt++)
                    mma8(acc[mt][nt], af[mt], bf[nt]);
        }

        if (pf) {
            stsA(s ^ 1);
            stsB(s ^ 1);
            __syncthreads();
        }
    }

    #pragma unroll
    for (int mt = 0; mt < 4; mt++) {
        const int row = bm + warp_m * 64 + mt * 16 + rl;
        #pragma unroll
        for (int nt = 0; nt < NT; nt++) {
            const int col = bn + warp_n * (NT * 8) + nt * 8 + 2 * q;
            float b0 = 0.f, b1 = 0.f;
            if (bias) { b0 = bias[col]; b1 = bias[col + 1]; }
            float v0 = acc[mt][nt][0] + b0, v1 = acc[mt][nt][1] + b1;
            float v2 = acc[mt][nt][2] + b0, v3 = acc[mt][nt][3] + b1;
            if (RELU) {
                v0 = fmaxf(v0, 0.f); v1 = fmaxf(v1, 0.f);
                v2 = fmaxf(v2, 0.f); v3 = fmaxf(v3, 0.f);
            }
            if (RES) {
                const float* r0p = res + (size_t)row * ldres + col;
                const float* r1p = res + (size_t)(row + 8) * ldres + col;
                v0 += r0p[0]; v1 += r0p[1]; v2 += r1p[0]; v3 += r1p[1];
            }
            if (TRANSH) {
                Ct[(size_t)col       * Mrows + row    ] = __float2half_rn(v0);
                Ct[(size_t)(col + 1) * Mrows + row    ] = __float2half_rn(v1);
                Ct[(size_t)col       * Mrows + row + 8] = __float2half_rn(v2);
                Ct[(size_t)(col + 1) * Mrows + row + 8] = __float2half_rn(v3);
            } else {
                *(float2*)&C[(size_t)row * ldc + col] = make_float2(v0, v1);
                *(float2*)&C[(size_t)(row + 8) * ldc + col] = make_float2(v2, v3);
            }
        }
    }
}

// ---------------------------------------------------------------------------
// LayerNorm (MWPToolkit: a*(x-mu)/(std_ddof1 + eps) + b) + residual
// ---------------------------------------------------------------------------
__global__ __launch_bounds__(256)
void ln_kernel(const float* __restrict__ x, const float* __restrict__ nodes,
               const float* __restrict__ ln_a, const float* __restrict__ ln_b,
               float* __restrict__ g)
{
    int warp = (blockIdx.x * blockDim.x + threadIdx.x) >> 5;
    int lane = threadIdx.x & 31;
    if (warp >= Mrows) return;
    const float* xr = x + (size_t)warp * 256;
    float v[8];
    float s = 0.f, ss = 0.f;
    #pragma unroll
    for (int j = 0; j < 8; j++) {
        v[j] = xr[lane + j * 32];
        s += v[j];
        ss += v[j] * v[j];
    }
    #pragma unroll
    for (int o = 16; o; o >>= 1) {
        s  += __shfl_xor_sync(0xffffffffu, s, o);
        ss += __shfl_xor_sync(0xffffffffu, ss, o);
    }
    float mu  = s * (1.f / 256.f);
    float var = (ss - 256.f * mu * mu) * (1.f / 255.f);
    float inv = 1.f / (sqrtf(fmaxf(var, 0.f)) + 1e-6f);
    const float* nd = nodes + (size_t)warp * 256;
    float* go = g + (size_t)warp * 256;
    #pragma unroll
    for (int j = 0; j < 8; j++) {
        int c = lane + j * 32;
        go[c] = ln_a[c] * (v[j] - mu) * inv + ln_b[c] + nd[c];
    }
}

// ---------------------------------------------------------------------------
// Launcher
// ---------------------------------------------------------------------------
extern "C" void kernel_launch(void* const* d_in, const int* in_sizes, int n_in,
                              void* d_out, int out_size)
{
    const float* nodes = (const float*)d_in[0];
    const int*   graph = (const int*)d_in[1];
    const float* Wg1   = (const float*)d_in[2];
    const float* bg1   = (const float*)d_in[3];
    const float* Wg2   = (const float*)d_in[4];
    const float* bg2   = (const float*)d_in[5];
    const float* Wf1   = (const float*)d_in[6];
    const float* bf1   = (const float*)d_in[7];
    const float* Wf2   = (const float*)d_in[8];
    const float* bf2   = (const float*)d_in[9];
    const float* ln_a  = (const float*)d_in[10];
    const float* ln_b  = (const float*)d_in[11];
    float* out = (float*)d_out;

    __half *adjh, *sup1t, *sup2t;
    float *h1, *h2c, *g, *ff1, *Wc1, *W2bd, *bc1, *bc2;
    cudaGetSymbolAddress((void**)&adjh,  d_adjh);
    cudaGetSymbolAddress((void**)&sup1t, d_sup1t);
    cudaGetSymbolAddress((void**)&sup2t, d_sup2t);
    cudaGetSymbolAddress((void**)&h1,    d_h1);
    cudaGetSymbolAddress((void**)&h2c,   d_h2c);
    cudaGetSymbolAddress((void**)&g,     d_g);
    cudaGetSymbolAddress((void**)&ff1,   d_ff1);
    cudaGetSymbolAddress((void**)&Wc1,   d_Wc1);
    cudaGetSymbolAddress((void**)&W2bd,  d_W2bd);
    cudaGetSymbolAddress((void**)&bc1,   d_bc1);
    cudaGetSymbolAddress((void**)&bc2,   d_bc2);

    // smem sizes
    const int ADJSM = 4 * ((128 + 256) * 128);            // 196,608 B (both tiles)
    const int DEN8  = 2 * (128 * 32 + 32 * (256 + 8)) * 4; // 100,352 B
    cudaFuncSetAttribute(adj_gemm_h16<128, 256, 2, 4, true>,
                         cudaFuncAttributeMaxDynamicSharedMemorySize, ADJSM);
    cudaFuncSetAttribute(adj_gemm_h16<256, 128, 2, 4, false>,
                         cudaFuncAttributeMaxDynamicSharedMemorySize, ADJSM);
    cudaFuncSetAttribute(dense_gemm<8, false, false, true>,
                         cudaFuncAttributeMaxDynamicSharedMemorySize, DEN8);
    cudaFuncSetAttribute(dense_gemm<8, true, false, false>,
                         cudaFuncAttributeMaxDynamicSharedMemorySize, DEN8);
    cudaFuncSetAttribute(dense_gemm<8, false, true, false>,
                         cudaFuncAttributeMaxDynamicSharedMemorySize, DEN8);

    // 0) adj passthrough (int -> float) + fp16 copies of slices {1,4}
    conv_adj<<<81920, 256>>>(graph, out, adjh, (int)(ADJ_ELEMS / 4));

    // 1) weight packing
    pack_w<<<1024, 256>>>(Wg1, bg1, Wg2, bg2);

    // 2) sup1^T (fp16) = (nodes @ Wc1)^T        (16384x256)@(256x1024)
    dense_gemm<8, false, false, true><<<dim3(4, 128, 1), 256, DEN8>>>(
        nodes, 256, Wc1, 1024, nullptr, nullptr, 0, nullptr, 0, sup1t, 256);

    // 3) h1 = relu(adj @ sup1 + bc1)   fp16 MMA, 32 batches (1024x1024)@(1024x512)
    adj_gemm_h16<128, 256, 2, 4, true><<<dim3(2, 8, 32), 256, ADJSM>>>(
        adjh, sup1t, bc1, h1, 1024, 512);

    // 4) sup2^T (fp16) = (h1 @ W2bd)^T          (16384x1024)@(1024x256)
    dense_gemm<8, false, false, true><<<dim3(1, 128, 1), 256, DEN8>>>(
        h1, 1024, W2bd, 256, nullptr, nullptr, 0, nullptr, 0, sup2t, 1024);

    // 5) h2 = adj @ sup2 + bc2         fp16 MMA, 32 batches (1024x1024)@(1024x128)
    //    128 CTAs = single wave
    adj_gemm_h16<256, 128, 2, 4, false><<<dim3(1, 4, 32), 256, ADJSM>>>(
        adjh, sup2t, bc2, h2c, 256, 128);

    // 6) g = LN(h2cat) + nodes
    ln_kernel<<<2048, 256>>>(h2c, nodes, ln_a, ln_b, g);

    // 7) ff1 = relu(g @ Wf1 + bf1)
    dense_gemm<8, true, false, false><<<dim3(1, 128, 1), 256, DEN8>>>(
        g, 256, Wf1, 256, bf1, nullptr, 0, ff1, 256, nullptr, 256);

    // 8) out = ff1 @ Wf2 + bf2 + g
    dense_gemm<8, false, true, false><<<dim3(1, 128, 1), 256, DEN8>>>(
        ff1, 256, Wf2, 256, bf2, g, 256, out + ADJ_ELEMS, 256, nullptr, 256);
}